// round 10
// baseline (speedup 1.0000x reference)
#include <cuda_runtime.h>
#include <cuda_bf16.h>
#include <mma.h>
#include <cstdint>

using namespace nvcuda;

#define BB 2
#define EPS 1e-7f

// ---------------------------------------------------------------------------
// scratch layout (floats)
// ---------------------------------------------------------------------------
#define SZ_T1P   16777216ull
#define SZ_F1P   16777216ull
#define SZ_T2P    8388608ull
#define SZ_F2P    8388608ull
#define SZ_T3P    3145728ull
#define SZ_F3P    3145728ull

#define O_T1_0   0ull
#define O_T1_1   (O_T1_0 + SZ_T1P)
#define O_F1_0   (O_T1_1 + SZ_T1P)
#define O_F1_1   (O_F1_0 + SZ_F1P)
#define O_T2_0   (O_F1_1 + SZ_F1P)
#define O_T2_1   (O_T2_0 + SZ_T2P)
#define O_F2_0   (O_T2_1 + SZ_T2P)
#define O_F2_1   (O_F2_0 + SZ_F2P)
#define O_T3_0   (O_F2_1 + SZ_F2P)
#define O_T3_1   (O_T3_0 + SZ_T3P)
#define O_F3_0   (O_T3_1 + SZ_T3P)
#define O_F3_1   (O_F3_0 + SZ_F3P)
#define O_Z      (O_F3_1 + SZ_F3P)
#define O_ZR1    (O_Z + 524288ull)
#define O_ZR2    (O_ZR1 + 131072ull)
#define O_ACC    (O_ZR2 + 32768ull)
#define ACC_PER_DIR 2064384ull
#define ACC_TOTAL   (2ull * ACC_PER_DIR)
#define SCRATCH_TOTAL (O_ACC + ACC_TOTAL)

__device__ float g_scratch[SCRATCH_TOTAL];

// ---------------------------------------------------------------------------
// cp.async helpers (used by fp32 conv1)
// ---------------------------------------------------------------------------
__device__ __forceinline__ void cp_async4(uint32_t smem_dst, const void* gsrc, bool pred)
{
    int sz = pred ? 4 : 0;
    asm volatile("cp.async.ca.shared.global [%0], [%1], 4, %2;\n"
                 :: "r"(smem_dst), "l"(gsrc), "r"(sz));
}
__device__ __forceinline__ void cp_commit() { asm volatile("cp.async.commit_group;\n"); }
template <int N>
__device__ __forceinline__ void cp_wait() { asm volatile("cp.async.wait_group %0;\n" :: "n"(N)); }

// ---------------------------------------------------------------------------
// fp32 conv (kept for conv1 only, IC=3)
// ---------------------------------------------------------------------------
template <int IC, int STRIDE, int PY, int CHUNK>
__global__ __launch_bounds__(256, 2)
void conv3x3_k(const float* __restrict__ in0, const float* __restrict__ in1,
               const float* __restrict__ wgt,
               const float* __restrict__ bias, const float* __restrict__ prelu_a,
               int aidx, float* __restrict__ out0, float* __restrict__ out1,
               int Hin, int Win, int OC, int ocBlocks)
{
    static_assert(IC % CHUNK == 0, "IC % CHUNK");
    constexpr int PX = 2;
    constexpr int OUT_TW = 16;
    constexpr int OUT_TH = 8 * PY;
    constexpr int TS_W = OUT_TW * STRIDE + 2;
    constexpr int TS_H = OUT_TH * STRIDE + 2;
    constexpr int TSZ  = TS_W * TS_H;
    constexpr int PW = (PX - 1) * STRIDE + 3;
    constexpr int PH = (PY - 1) * STRIDE + 3;
    constexpr int NCH = IC / CHUNK;
    constexpr int BUF = CHUNK * TSZ + CHUNK * 288;

    extern __shared__ __align__(32) float s_mem[];

    const int tid = threadIdx.x;
    const int oo  = tid & 3;
    const int slot = tid >> 2;
    const int sx = slot & 7;
    const int sy = slot >> 3;

    const int zper = BB * ocBlocks;
    const int img  = blockIdx.z / zper;
    const int rem  = blockIdx.z - img * zper;
    const int b    = rem / ocBlocks;
    const int ocb  = rem - b * ocBlocks;
    const float* __restrict__ in  = img ? in1 : in0;
    float* __restrict__ out = img ? out1 : out0;

    const int oc0 = ocb * 32;
    const int Hout = Hin / STRIDE;
    const int Wout = Win / STRIDE;

    const int ox = blockIdx.x * OUT_TW + sx * PX;
    const int oy = blockIdx.y * OUT_TH + sy * PY;
    const int ix0 = blockIdx.x * OUT_TW * STRIDE - 1;
    const int iy0 = blockIdx.y * OUT_TH * STRIDE - 1;

    const int ly = sy * PY * STRIDE;
    const int lx = sx * PX * STRIDE;

    auto stage = [&](int ci, int bufIdx) {
        float* sb = s_mem + bufIdx * BUF;
        const uint32_t s_in_a = (uint32_t)__cvta_generic_to_shared(sb);
        const uint32_t s_w_a  = (uint32_t)__cvta_generic_to_shared(sb + CHUNK * TSZ);
        const int cb = ci * CHUNK;
#pragma unroll 4
        for (int i = tid; i < CHUNK * TSZ; i += 256) {
            int c = i / TSZ;
            int j = i - c * TSZ;
            int gy = iy0 + j / TS_W;
            int gx = ix0 + j % TS_W;
            bool ok = (gy >= 0 && gy < Hin && gx >= 0 && gx < Win);
            const float* src = in + ((size_t)(b * IC + cb + c)) * Hin * Win
                                  + (ok ? (gy * Win + gx) : 0);
            cp_async4(s_in_a + 4u * i, src, ok);
        }
#pragma unroll 4
        for (int i = tid; i < CHUNK * 288; i += 256) {
            int c = i / 288;
            int r = i - c * 288;
            int k = r >> 5, oc = r & 31;
            cp_async4(s_w_a + 4u * i,
                      &wgt[((size_t)(oc0 + oc) * IC + cb + c) * 9 + k], true);
        }
        cp_commit();
    };

    float acc[8][PX * PY];
#pragma unroll
    for (int o = 0; o < 8; o++)
#pragma unroll
        for (int p = 0; p < PX * PY; p++) acc[o][p] = 0.f;

    stage(0, 0);

    for (int ci = 0; ci < NCH; ci++) {
        const int cur = ci & 1;
        if (ci + 1 < NCH) stage(ci + 1, cur ^ 1);

        if (ci + 1 < NCH) cp_wait<1>(); else cp_wait<0>();
        __syncthreads();

        const float* s_in = s_mem + cur * BUF;
        const float* s_w  = s_in + CHUNK * TSZ;

#pragma unroll
        for (int c = 0; c < CHUNK; c++) {
            float v[PH][PW];
#pragma unroll
            for (int r = 0; r < PH; r++)
#pragma unroll
                for (int cc = 0; cc < PW; cc++)
                    v[r][cc] = s_in[c * TSZ + (ly + r) * TS_W + lx + cc];

#pragma unroll
            for (int k = 0; k < 9; k++) {
                const int ky = k / 3, kx = k % 3;
                const float4 wA = *reinterpret_cast<const float4*>(&s_w[c * 288 + k * 32 + oo * 8]);
                const float4 wB = *reinterpret_cast<const float4*>(&s_w[c * 288 + k * 32 + oo * 8 + 4]);
                const float w8[8] = {wA.x, wA.y, wA.z, wA.w, wB.x, wB.y, wB.z, wB.w};
#pragma unroll
                for (int o = 0; o < 8; o++)
#pragma unroll
                    for (int py = 0; py < PY; py++)
#pragma unroll
                        for (int px = 0; px < PX; px++)
                            acc[o][py * PX + px] =
                                fmaf(v[py * STRIDE + ky][px * STRIDE + kx], w8[o],
                                     acc[o][py * PX + px]);
            }
        }
        __syncthreads();
    }

    const float slope = prelu_a[aidx];
#pragma unroll
    for (int o = 0; o < 8; o++) {
        const int oc = oc0 + oo * 8 + o;
        const float bv = bias[oc];
        float* op = out + (((size_t)b * OC + oc) * Hout) * Wout;
#pragma unroll
        for (int py = 0; py < PY; py++) {
            float v0 = acc[o][py * PX + 0] + bv;
            float v1 = acc[o][py * PX + 1] + bv;
            if (v0 < 0.f) v0 *= slope;
            if (v1 < 0.f) v1 *= slope;
            *reinterpret_cast<float2*>(&op[(size_t)(oy + py) * Wout + ox]) =
                make_float2(v0, v1);
        }
    }
}

// ---------------------------------------------------------------------------
// Tensor-core implicit-GEMM 3x3 conv + PReLU (layers 2..6).
// bf16 hi/lo split, 3 MMAs (hi*hi + hi*lo + lo*hi), fp32 accumulate.
// Tile: M=64 pixels (one output-row segment) x N=32 oc. K-chunk = 16 ic = 144.
// A staged col-major [k][m] (LDA=72), B as [n][k] (LDB=152).
// ---------------------------------------------------------------------------
#define LDA 72
#define LDB 152
#define LDD 36
#define A_ELEMS (144 * LDA)
#define B_ELEMS (32 * LDB)
#define WMMA_SMEM ((2 * A_ELEMS + 2 * B_ELEMS) * 2)   // bytes

template <int IC, int STRIDE>
__global__ __launch_bounds__(256)
void conv_wmma_k(const float* __restrict__ in0, const float* __restrict__ in1,
                 const float* __restrict__ wgt,
                 const float* __restrict__ bias, const float* __restrict__ prelu_a,
                 int aidx, float* __restrict__ out0, float* __restrict__ out1,
                 int Hin, int Win, int OC, int ocBlocks)
{
    static_assert(IC % 16 == 0, "IC % 16");
    extern __shared__ __align__(32) char smem_raw[];
    __nv_bfloat16* A_hi = (__nv_bfloat16*)smem_raw;
    __nv_bfloat16* A_lo = A_hi + A_ELEMS;
    __nv_bfloat16* B_hi = A_lo + A_ELEMS;
    __nv_bfloat16* B_lo = B_hi + B_ELEMS;

    const int tid = threadIdx.x;
    const int w   = tid >> 5;
    const int m0  = (w & 3) * 16;
    const int n0  = (w >> 2) * 16;

    const int zper = BB * ocBlocks;
    const int img  = blockIdx.z / zper;
    const int rem  = blockIdx.z - img * zper;
    const int b    = rem / ocBlocks;
    const int ocb  = rem - b * ocBlocks;
    const float* __restrict__ in  = img ? in1 : in0;
    float* __restrict__ out = img ? out1 : out0;

    const int oc0g = ocb * 32;
    const int Hout = Hin / STRIDE;
    const int Wout = Win / STRIDE;
    const int x0 = blockIdx.x * 64;
    const int oy = blockIdx.y;
    const int HWin = Hin * Win;

    wmma::fragment<wmma::accumulator, 16, 16, 16, float> acc;
    wmma::fill_fragment(acc, 0.f);

    for (int cb = 0; cb < IC; cb += 16) {
        __syncthreads();
        // ---- fill A (im2col, col-major [kidx][m]), hi/lo bf16 ----
        for (int idx = tid; idx < 64 * 144; idx += 256) {
            int m = idx & 63, kidx = idx >> 6;
            int icc = kidx / 9, tap = kidx - icc * 9;
            int ky = tap / 3, kx = tap - ky * 3;
            int iy = oy * STRIDE + ky - 1;
            int ix = (x0 + m) * STRIDE + kx - 1;
            float v = 0.f;
            if (iy >= 0 && iy < Hin && ix >= 0 && ix < Win)
                v = in[(size_t)(b * IC + cb + icc) * HWin + iy * Win + ix];
            __nv_bfloat16 h = __float2bfloat16(v);
            __nv_bfloat16 l = __float2bfloat16(v - __bfloat162float(h));
            A_hi[kidx * LDA + m] = h;
            A_lo[kidx * LDA + m] = l;
        }
        // ---- fill B ([oc][kidx]) ----
        for (int idx = tid; idx < 32 * 144; idx += 256) {
            int kidx = idx % 144;
            int oc   = idx / 144;
            int icc = kidx / 9, tap = kidx - icc * 9;
            float v = wgt[((size_t)(oc0g + oc) * IC + cb + icc) * 9 + tap];
            __nv_bfloat16 h = __float2bfloat16(v);
            __nv_bfloat16 l = __float2bfloat16(v - __bfloat162float(h));
            B_hi[oc * LDB + kidx] = h;
            B_lo[oc * LDB + kidx] = l;
        }
        __syncthreads();

#pragma unroll
        for (int ks = 0; ks < 9; ks++) {
            wmma::fragment<wmma::matrix_a, 16, 16, 16, __nv_bfloat16, wmma::col_major> ah, al;
            wmma::fragment<wmma::matrix_b, 16, 16, 16, __nv_bfloat16, wmma::col_major> bh, bl;
            wmma::load_matrix_sync(ah, A_hi + ks * 16 * LDA + m0, LDA);
            wmma::load_matrix_sync(al, A_lo + ks * 16 * LDA + m0, LDA);
            wmma::load_matrix_sync(bh, B_hi + n0 * LDB + ks * 16, LDB);
            wmma::load_matrix_sync(bl, B_lo + n0 * LDB + ks * 16, LDB);
            wmma::mma_sync(acc, ah, bh, acc);
            wmma::mma_sync(acc, ah, bl, acc);
            wmma::mma_sync(acc, al, bh, acc);
        }
    }

    // ---- epilogue via smem bounce (aliases A region) ----
    __syncthreads();
    float* D_s = (float*)smem_raw;           // 64 x LDD
    wmma::store_matrix_sync(D_s + m0 * LDD + n0, acc, LDD, wmma::mem_row_major);
    __syncthreads();

    const float slope = prelu_a[aidx];
    for (int idx = tid; idx < 64 * 32; idx += 256) {
        int m = idx & 63, oc = idx >> 6;
        float v = D_s[m * LDD + oc] + bias[oc0g + oc];
        if (v < 0.f) v *= slope;
        out[((size_t)(b * OC + oc0g + oc) * Hout + oy) * Wout + x0 + m] = v;
    }
}

// ---------------------------------------------------------------------------
// z = param_scale * mean_c |p0 - backwarp(p1, flow)|
// ---------------------------------------------------------------------------
__global__ void z_kernel(const float* __restrict__ i0, const float* __restrict__ i1,
                         const float* __restrict__ flow, const float* __restrict__ pscale,
                         float* __restrict__ z, int h, int w, int n)
{
    int p = blockIdx.x * 256 + threadIdx.x;
    if (p >= n) return;
    const int hw = h * w;
    const int b = p / hw, pp = p % hw;
    const int y = pp / w, x = pp - y * w;

    float f0 = flow[((size_t)b * 2 + 0) * hw + pp];
    float f1 = flow[((size_t)b * 2 + 1) * hw + pp];
    float px = fminf(fmaxf((float)x + f0, 0.f), (float)(w - 1));
    float py = fminf(fmaxf((float)y + f1, 0.f), (float)(h - 1));
    float x0f = floorf(px), y0f = floorf(py);
    int x0 = (int)x0f, y0 = (int)y0f;
    int x1 = min(x0 + 1, w - 1), y1 = min(y0 + 1, h - 1);
    float wx = px - x0f, wy = py - y0f;
    float w00 = (1.f - wx) * (1.f - wy), w10 = wx * (1.f - wy);
    float w01 = (1.f - wx) * wy,        w11 = wx * wy;

    float err = 0.f;
#pragma unroll
    for (int c = 0; c < 3; c++) {
        const float* sp = i1 + ((size_t)(b * 3 + c)) * hw;
        float g = sp[y0 * w + x0] * w00 + sp[y0 * w + x1] * w10 +
                  sp[y1 * w + x0] * w01 + sp[y1 * w + x1] * w11;
        float pg = 2.f * g - 1.f;
        float p0 = 2.f * i0[((size_t)(b * 3 + c)) * hw + pp] - 1.f;
        err += fabsf(p0 - pg);
    }
    err *= (1.f / 3.f);
    z[p] = pscale[0] * err;
}

__global__ void resize_k(const float* __restrict__ in, float* __restrict__ out,
                         int hi, int wi, int ho, int wo, int n)
{
    int p = blockIdx.x * 256 + threadIdx.x;
    if (p >= n) return;
    const int hwO = ho * wo;
    const int b = p / hwO, pp = p % hwO;
    const int y = pp / wo, x = pp - y * wo;

    float sy = (float)hi / (float)ho;
    float sx = (float)wi / (float)wo;
    float py = fminf(fmaxf(((float)y + 0.5f) * sy - 0.5f, 0.f), (float)(hi - 1));
    float px = fminf(fmaxf(((float)x + 0.5f) * sx - 0.5f, 0.f), (float)(wi - 1));
    float y0f = floorf(py), x0f = floorf(px);
    int y0 = (int)y0f, x0 = (int)x0f;
    int y1 = min(y0 + 1, hi - 1), x1 = min(x0 + 1, wi - 1);
    float wy = py - y0f, wx = px - x0f;

    const float* sp = in + (size_t)b * hi * wi;
    float r0 = sp[y0 * wi + x0] * (1.f - wx) + sp[y0 * wi + x1] * wx;
    float r1 = sp[y1 * wi + x0] * (1.f - wx) + sp[y1 * wi + x1] * wx;
    out[p] = r0 * (1.f - wy) + r1 * wy;
}

__global__ void splat_k(const float* __restrict__ flow, const float* __restrict__ zz,
                        const float* __restrict__ tvec, int oneMinus,
                        float* __restrict__ acc, int h, int w, int n)
{
    int p = blockIdx.x * 256 + threadIdx.x;
    if (p >= n) return;
    const int hw = h * w;
    const int b = p / hw, pp = p % hw;
    const int y = pp / w, x = pp - y * w;

    float tt = tvec[b];
    if (oneMinus) tt = 1.f - tt;
    float f0 = tt * flow[((size_t)b * 2 + 0) * hw + pp];
    float f1 = tt * flow[((size_t)b * 2 + 1) * hw + pp];
    float ez = expf(zz[(size_t)b * hw + pp]);
    float v0 = -f0 * ez, v1 = -f1 * ez;

    float fx = (float)x + f0, fy = (float)y + f1;
    float x0f = floorf(fx), y0f = floorf(fy);
    int x0 = (int)x0f, y0 = (int)y0f;
    int x1 = x0 + 1, y1 = y0 + 1;
    float wx1 = fx - x0f, wy1 = fy - y0f;
    float wx0 = 1.f - wx1, wy0 = 1.f - wy1;

    float* a0 = acc + (size_t)b * 3 * hw;
    int cx[4] = {x0, x1, x0, x1};
    int cy[4] = {y0, y0, y1, y1};
    float cw[4] = {wx0 * wy0, wx1 * wy0, wx0 * wy1, wx1 * wy1};
#pragma unroll
    for (int k = 0; k < 4; k++) {
        if (cx[k] >= 0 && cx[k] < w && cy[k] >= 0 && cy[k] < h) {
            int q = cy[k] * w + cx[k];
            float wt = cw[k];
            atomicAdd(a0 + q, v0 * wt);
            atomicAdd(a0 + hw + q, v1 * wt);
            atomicAdd(a0 + 2 * hw + q, ez * wt);
        }
    }
}

__global__ void backwarp_out_k(const float* __restrict__ src, int C,
                               const float* __restrict__ acc, float* __restrict__ out,
                               int CT, int c0, int h, int w, int n)
{
    int p = blockIdx.x * 256 + threadIdx.x;
    if (p >= n) return;
    const int hw = h * w;
    const int b = p / hw, pp = p % hw;
    const int y = pp / w, x = pp - y * w;

    const float* ab = acc + (size_t)b * 3 * hw;
    float d  = ab[2 * hw + pp] + EPS;
    float f0 = ab[pp] / d;
    float f1 = ab[hw + pp] / d;

    float px = fminf(fmaxf((float)x + f0, 0.f), (float)(w - 1));
    float py = fminf(fmaxf((float)y + f1, 0.f), (float)(h - 1));
    float x0f = floorf(px), y0f = floorf(py);
    int x0 = (int)x0f, y0 = (int)y0f;
    int x1 = min(x0 + 1, w - 1), y1 = min(y0 + 1, h - 1);
    float wx = px - x0f, wy = py - y0f;
    float w00 = (1.f - wx) * (1.f - wy), w10 = wx * (1.f - wy);
    float w01 = (1.f - wx) * wy,        w11 = wx * wy;

    int cbeg = blockIdx.y * 8;
    int cend = min(cbeg + 8, C);
#pragma unroll 4
    for (int c = cbeg; c < cend; c++) {
        const float* sp = src + ((size_t)b * C + c) * hw;
        float g = sp[y0 * w + x0] * w00 + sp[y0 * w + x1] * w10 +
                  sp[y1 * w + x0] * w01 + sp[y1 * w + x1] * w11;
        out[(((size_t)b * CT + c0 + c) * h + y) * w + x] = g;
    }
}

// ---------------------------------------------------------------------------
// Orchestration
// ---------------------------------------------------------------------------
static inline int cdiv(int a, int b) { return (a + b - 1) / b; }

static inline int conv_smem(int STRIDE, int PY, int CHUNK)
{
    int tsw = 16 * STRIDE + 2;
    int tsh = 8 * PY * STRIDE + 2;
    return 2 * CHUNK * (tsw * tsh + 288) * 4;
}

extern "C" void kernel_launch(void* const* d_in, const int* in_sizes, int n_in,
                              void* d_out, int out_size)
{
    const float* in0   = (const float*)d_in[0];
    const float* in1   = (const float*)d_in[1];
    const float* tvec  = (const float*)d_in[2];
    const float* f01[3] = {(const float*)d_in[3], (const float*)d_in[4], (const float*)d_in[5]};
    const float* f10[3] = {(const float*)d_in[6], (const float*)d_in[7], (const float*)d_in[8]};
    const float* W[6]  = {(const float*)d_in[9],  (const float*)d_in[11], (const float*)d_in[13],
                          (const float*)d_in[15], (const float*)d_in[17], (const float*)d_in[19]};
    const float* Bs[6] = {(const float*)d_in[10], (const float*)d_in[12], (const float*)d_in[14],
                          (const float*)d_in[16], (const float*)d_in[18], (const float*)d_in[20]};
    const float* prelu  = (const float*)d_in[21];
    const float* pscale = (const float*)d_in[22];
    float* out = (float*)d_out;

    float* S = nullptr;
    cudaGetSymbolAddress((void**)&S, g_scratch);

    const int sm1 = conv_smem(1, 4, 3);
    cudaFuncSetAttribute((const void*)conv3x3_k<3, 1, 4, 3>, cudaFuncAttributeMaxDynamicSharedMemorySize, sm1);
    cudaFuncSetAttribute((const void*)conv_wmma_k<32, 1>, cudaFuncAttributeMaxDynamicSharedMemorySize, WMMA_SMEM);
    cudaFuncSetAttribute((const void*)conv_wmma_k<32, 2>, cudaFuncAttributeMaxDynamicSharedMemorySize, WMMA_SMEM);
    cudaFuncSetAttribute((const void*)conv_wmma_k<64, 1>, cudaFuncAttributeMaxDynamicSharedMemorySize, WMMA_SMEM);
    cudaFuncSetAttribute((const void*)conv_wmma_k<64, 2>, cudaFuncAttributeMaxDynamicSharedMemorySize, WMMA_SMEM);
    cudaFuncSetAttribute((const void*)conv_wmma_k<96, 1>, cudaFuncAttributeMaxDynamicSharedMemorySize, WMMA_SMEM);

    cudaMemsetAsync(S + O_ACC, 0, sizeof(float) * ACC_TOTAL, 0);

    // ---- conv1 (fp32, IC=3), both images batched ----
    conv3x3_k<3, 1, 4, 3><<<dim3(32, 16, 4), 256, sm1>>>(in0, in1, W[0], Bs[0], prelu, 0,
                                                          S + O_T1_0, S + O_T1_1, 512, 512, 32, 1);

    // ---- conv2..6 (tensor-core, bf16 hi/lo 3-MMA) ----
    // grid: (Wout/64, Hout, BB*2img*(OC/32))
    conv_wmma_k<32, 1><<<dim3(8, 512, 4),  256, WMMA_SMEM>>>(S + O_T1_0, S + O_T1_1, W[1], Bs[1], prelu, 1,
                                                              S + O_F1_0, S + O_F1_1, 512, 512, 32, 1);
    conv_wmma_k<32, 2><<<dim3(4, 256, 8),  256, WMMA_SMEM>>>(S + O_F1_0, S + O_F1_1, W[2], Bs[2], prelu, 2,
                                                              S + O_T2_0, S + O_T2_1, 512, 512, 64, 2);
    conv_wmma_k<64, 1><<<dim3(4, 256, 8),  256, WMMA_SMEM>>>(S + O_T2_0, S + O_T2_1, W[3], Bs[3], prelu, 3,
                                                              S + O_F2_0, S + O_F2_1, 256, 256, 64, 2);
    conv_wmma_k<64, 2><<<dim3(2, 128, 12), 256, WMMA_SMEM>>>(S + O_F2_0, S + O_F2_1, W[4], Bs[4], prelu, 4,
                                                              S + O_T3_0, S + O_T3_1, 256, 256, 96, 3);
    conv_wmma_k<96, 1><<<dim3(2, 128, 12), 256, WMMA_SMEM>>>(S + O_T3_0, S + O_T3_1, W[5], Bs[5], prelu, 5,
                                                              S + O_F3_0, S + O_F3_1, 128, 128, 96, 3);

    float* L0 = out;                 // (B,70,512,512)
    float* L1 = out + 36700160ull;   // (B,128,256,256)
    float* L2 = out + 53477376ull;   // (B,192,128,128)

    for (int dir = 0; dir < 2; dir++) {
        const float* i0 = dir ? in1 : in0;
        const float* i1sec = dir ? in0 : in1;
        const float* const* fl = dir ? f10 : f01;
        const float* fea1 = S + (dir ? O_F1_1 : O_F1_0);
        const float* fea2 = S + (dir ? O_F2_1 : O_F2_0);
        const float* fea3 = S + (dir ? O_F3_1 : O_F3_0);

        float* acc0 = S + O_ACC + (size_t)dir * ACC_PER_DIR;
        float* acc1 = acc0 + 1572864;
        float* acc2 = acc0 + 1966080;
        float* accS[3] = {acc0, acc1, acc2};

        const int n0 = BB * 512 * 512;
        z_kernel<<<cdiv(n0, 256), 256>>>(i0, i1sec, fl[0], pscale, S + O_Z, 512, 512, n0);
        const int nr1 = BB * 256 * 256, nr2 = BB * 128 * 128;
        resize_k<<<cdiv(nr1, 256), 256>>>(S + O_Z, S + O_ZR1, 512, 512, 256, 256, nr1);
        resize_k<<<cdiv(nr2, 256), 256>>>(S + O_Z, S + O_ZR2, 512, 512, 128, 128, nr2);

        for (int s = 0; s < 3; s++) {
            const int hh = 512 >> s, ww = 512 >> s;
            const int hw = hh * ww, n = BB * hw;
            const float* zl = (s == 0) ? (S + O_Z) : ((s == 1) ? (S + O_ZR1) : (S + O_ZR2));

            splat_k<<<cdiv(n, 256), 256>>>(fl[s], zl, tvec, dir, accS[s], hh, ww, n);

            if (s == 0) {
                backwarp_out_k<<<dim3(cdiv(n, 256), 1), 256>>>(i0,   3,  accS[s], L0, 70, dir ? 35 : 0, hh, ww, n);
                backwarp_out_k<<<dim3(cdiv(n, 256), 4), 256>>>(fea1, 32, accS[s], L0, 70, dir ? 38 : 3, hh, ww, n);
            } else if (s == 1) {
                backwarp_out_k<<<dim3(cdiv(n, 256), 8), 256>>>(fea2, 64, accS[s], L1, 128, dir ? 64 : 0, hh, ww, n);
            } else {
                backwarp_out_k<<<dim3(cdiv(n, 256), 12), 256>>>(fea3, 96, accS[s], L2, 192, dir ? 96 : 0, hh, ww, n);
            }
        }
    }
}

// round 11
// speedup vs baseline: 1.5174x; 1.5174x over previous
#include <cuda_runtime.h>
#include <cstdint>

#define BB 2
#define EPS 1e-7f

// ---------------------------------------------------------------------------
// scratch layout (floats)
// ---------------------------------------------------------------------------
#define SZ_T1P   16777216ull
#define SZ_F1P   16777216ull
#define SZ_T2P    8388608ull
#define SZ_F2P    8388608ull
#define SZ_T3P    3145728ull
#define SZ_F3P    3145728ull

#define O_T1_0   0ull
#define O_T1_1   (O_T1_0 + SZ_T1P)
#define O_F1_0   (O_T1_1 + SZ_T1P)
#define O_F1_1   (O_F1_0 + SZ_F1P)
#define O_T2_0   (O_F1_1 + SZ_F1P)
#define O_T2_1   (O_T2_0 + SZ_T2P)
#define O_F2_0   (O_T2_1 + SZ_T2P)
#define O_F2_1   (O_F2_0 + SZ_F2P)
#define O_T3_0   (O_F2_1 + SZ_F2P)
#define O_T3_1   (O_T3_0 + SZ_T3P)
#define O_F3_0   (O_T3_1 + SZ_T3P)
#define O_F3_1   (O_F3_0 + SZ_F3P)
// z buffers now hold BOTH directions: [dir][b][hw]
#define O_Z      (O_F3_1 + SZ_F3P)
#define O_ZR1    (O_Z + 1048576ull)
#define O_ZR2    (O_ZR1 + 262144ull)
#define O_ACC    (O_ZR2 + 65536ull)
#define ACC_PER_DIR 2064384ull
#define ACC_TOTAL   (2ull * ACC_PER_DIR)
#define SCRATCH_TOTAL (O_ACC + ACC_TOTAL)

__device__ float g_scratch[SCRATCH_TOTAL];

// ---------------------------------------------------------------------------
// cp.async helpers
// ---------------------------------------------------------------------------
__device__ __forceinline__ void cp_async4(uint32_t smem_dst, const void* gsrc, bool pred)
{
    int sz = pred ? 4 : 0;
    asm volatile("cp.async.ca.shared.global [%0], [%1], 4, %2;\n"
                 :: "r"(smem_dst), "l"(gsrc), "r"(sz));
}
__device__ __forceinline__ void cp_commit() { asm volatile("cp.async.commit_group;\n"); }
template <int N>
__device__ __forceinline__ void cp_wait() { asm volatile("cp.async.wait_group %0;\n" :: "n"(N)); }

// ---------------------------------------------------------------------------
// fp32 register-tiled 3x3 conv + PReLU (R9 form — ~97% of FFMA roofline).
// Both images batched in grid.z.
// ---------------------------------------------------------------------------
template <int IC, int STRIDE, int PY, int CHUNK>
__global__ __launch_bounds__(256, 2)
void conv3x3_k(const float* __restrict__ in0, const float* __restrict__ in1,
               const float* __restrict__ wgt,
               const float* __restrict__ bias, const float* __restrict__ prelu_a,
               int aidx, float* __restrict__ out0, float* __restrict__ out1,
               int Hin, int Win, int OC, int ocBlocks)
{
    static_assert(IC % CHUNK == 0, "IC % CHUNK");
    constexpr int PX = 2;
    constexpr int OUT_TW = 16;
    constexpr int OUT_TH = 8 * PY;
    constexpr int TS_W = OUT_TW * STRIDE + 2;
    constexpr int TS_H = OUT_TH * STRIDE + 2;
    constexpr int TSZ  = TS_W * TS_H;
    constexpr int PW = (PX - 1) * STRIDE + 3;
    constexpr int PH = (PY - 1) * STRIDE + 3;
    constexpr int NCH = IC / CHUNK;
    constexpr int BUF = CHUNK * TSZ + CHUNK * 288;

    extern __shared__ __align__(32) float s_mem[];

    const int tid = threadIdx.x;
    const int oo  = tid & 3;
    const int slot = tid >> 2;
    const int sx = slot & 7;
    const int sy = slot >> 3;

    const int zper = BB * ocBlocks;
    const int img  = blockIdx.z / zper;
    const int rem  = blockIdx.z - img * zper;
    const int b    = rem / ocBlocks;
    const int ocb  = rem - b * ocBlocks;
    const float* __restrict__ in  = img ? in1 : in0;
    float* __restrict__ out = img ? out1 : out0;

    const int oc0 = ocb * 32;
    const int Hout = Hin / STRIDE;
    const int Wout = Win / STRIDE;

    const int ox = blockIdx.x * OUT_TW + sx * PX;
    const int oy = blockIdx.y * OUT_TH + sy * PY;
    const int ix0 = blockIdx.x * OUT_TW * STRIDE - 1;
    const int iy0 = blockIdx.y * OUT_TH * STRIDE - 1;

    const int ly = sy * PY * STRIDE;
    const int lx = sx * PX * STRIDE;

    auto stage = [&](int ci, int bufIdx) {
        float* sb = s_mem + bufIdx * BUF;
        const uint32_t s_in_a = (uint32_t)__cvta_generic_to_shared(sb);
        const uint32_t s_w_a  = (uint32_t)__cvta_generic_to_shared(sb + CHUNK * TSZ);
        const int cb = ci * CHUNK;
#pragma unroll 4
        for (int i = tid; i < CHUNK * TSZ; i += 256) {
            int c = i / TSZ;
            int j = i - c * TSZ;
            int gy = iy0 + j / TS_W;
            int gx = ix0 + j % TS_W;
            bool ok = (gy >= 0 && gy < Hin && gx >= 0 && gx < Win);
            const float* src = in + ((size_t)(b * IC + cb + c)) * Hin * Win
                                  + (ok ? (gy * Win + gx) : 0);
            cp_async4(s_in_a + 4u * i, src, ok);
        }
#pragma unroll 4
        for (int i = tid; i < CHUNK * 288; i += 256) {
            int c = i / 288;
            int r = i - c * 288;
            int k = r >> 5, oc = r & 31;
            cp_async4(s_w_a + 4u * i,
                      &wgt[((size_t)(oc0 + oc) * IC + cb + c) * 9 + k], true);
        }
        cp_commit();
    };

    float acc[8][PX * PY];
#pragma unroll
    for (int o = 0; o < 8; o++)
#pragma unroll
        for (int p = 0; p < PX * PY; p++) acc[o][p] = 0.f;

    stage(0, 0);

    for (int ci = 0; ci < NCH; ci++) {
        const int cur = ci & 1;
        if (ci + 1 < NCH) stage(ci + 1, cur ^ 1);

        if (ci + 1 < NCH) cp_wait<1>(); else cp_wait<0>();
        __syncthreads();

        const float* s_in = s_mem + cur * BUF;
        const float* s_w  = s_in + CHUNK * TSZ;

#pragma unroll
        for (int c = 0; c < CHUNK; c++) {
            float v[PH][PW];
#pragma unroll
            for (int r = 0; r < PH; r++)
#pragma unroll
                for (int cc = 0; cc < PW; cc++)
                    v[r][cc] = s_in[c * TSZ + (ly + r) * TS_W + lx + cc];

#pragma unroll
            for (int k = 0; k < 9; k++) {
                const int ky = k / 3, kx = k % 3;
                const float4 wA = *reinterpret_cast<const float4*>(&s_w[c * 288 + k * 32 + oo * 8]);
                const float4 wB = *reinterpret_cast<const float4*>(&s_w[c * 288 + k * 32 + oo * 8 + 4]);
                const float w8[8] = {wA.x, wA.y, wA.z, wA.w, wB.x, wB.y, wB.z, wB.w};
#pragma unroll
                for (int o = 0; o < 8; o++)
#pragma unroll
                    for (int py = 0; py < PY; py++)
#pragma unroll
                        for (int px = 0; px < PX; px++)
                            acc[o][py * PX + px] =
                                fmaf(v[py * STRIDE + ky][px * STRIDE + kx], w8[o],
                                     acc[o][py * PX + px]);
            }
        }
        __syncthreads();
    }

    const float slope = prelu_a[aidx];
#pragma unroll
    for (int o = 0; o < 8; o++) {
        const int oc = oc0 + oo * 8 + o;
        const float bv = bias[oc];
        float* op = out + (((size_t)b * OC + oc) * Hout) * Wout;
#pragma unroll
        for (int py = 0; py < PY; py++) {
            float v0 = acc[o][py * PX + 0] + bv;
            float v1 = acc[o][py * PX + 1] + bv;
            if (v0 < 0.f) v0 *= slope;
            if (v1 < 0.f) v1 *= slope;
            *reinterpret_cast<float2*>(&op[(size_t)(oy + py) * Wout + ox]) =
                make_float2(v0, v1);
        }
    }
}

// ---------------------------------------------------------------------------
// z for BOTH directions: z[dir][b] = pscale * mean_c |p(i0) - backwarp(p(i1))|
// n = 2*BB*hw
// ---------------------------------------------------------------------------
__global__ void z_kernel(const float* __restrict__ in0, const float* __restrict__ in1,
                         const float* __restrict__ fA, const float* __restrict__ fB,
                         const float* __restrict__ pscale,
                         float* __restrict__ z, int h, int w, int n)
{
    int p = blockIdx.x * 256 + threadIdx.x;
    if (p >= n) return;
    const int hw = h * w;
    const int bb = p / hw, pp = p % hw;
    const int dir = bb / BB, b = bb - dir * BB;
    const int y = pp / w, x = pp - y * w;

    const float* i0 = dir ? in1 : in0;
    const float* i1 = dir ? in0 : in1;
    const float* flow = dir ? fB : fA;

    float f0 = flow[((size_t)b * 2 + 0) * hw + pp];
    float f1 = flow[((size_t)b * 2 + 1) * hw + pp];
    float px = fminf(fmaxf((float)x + f0, 0.f), (float)(w - 1));
    float py = fminf(fmaxf((float)y + f1, 0.f), (float)(h - 1));
    float x0f = floorf(px), y0f = floorf(py);
    int x0 = (int)x0f, y0 = (int)y0f;
    int x1 = min(x0 + 1, w - 1), y1 = min(y0 + 1, h - 1);
    float wx = px - x0f, wy = py - y0f;
    float w00 = (1.f - wx) * (1.f - wy), w10 = wx * (1.f - wy);
    float w01 = (1.f - wx) * wy,        w11 = wx * wy;

    float err = 0.f;
#pragma unroll
    for (int c = 0; c < 3; c++) {
        const float* sp = i1 + ((size_t)(b * 3 + c)) * hw;
        float g = sp[y0 * w + x0] * w00 + sp[y0 * w + x1] * w10 +
                  sp[y1 * w + x0] * w01 + sp[y1 * w + x1] * w11;
        float pg = 2.f * g - 1.f;
        float p0 = 2.f * i0[((size_t)(b * 3 + c)) * hw + pp] - 1.f;
        err += fabsf(p0 - pg);
    }
    err *= (1.f / 3.f);
    z[p] = pscale[0] * err;
}

// ---------------------------------------------------------------------------
// bilinear resize; batch dimension generic (b = p / hwO indexes [dir][b])
// ---------------------------------------------------------------------------
__global__ void resize_k(const float* __restrict__ in, float* __restrict__ out,
                         int hi, int wi, int ho, int wo, int n)
{
    int p = blockIdx.x * 256 + threadIdx.x;
    if (p >= n) return;
    const int hwO = ho * wo;
    const int b = p / hwO, pp = p % hwO;
    const int y = pp / wo, x = pp - y * wo;

    float sy = (float)hi / (float)ho;
    float sx = (float)wi / (float)wo;
    float py = fminf(fmaxf(((float)y + 0.5f) * sy - 0.5f, 0.f), (float)(hi - 1));
    float px = fminf(fmaxf(((float)x + 0.5f) * sx - 0.5f, 0.f), (float)(wi - 1));
    float y0f = floorf(py), x0f = floorf(px);
    int y0 = (int)y0f, x0 = (int)x0f;
    int y1 = min(y0 + 1, hi - 1), x1 = min(x0 + 1, wi - 1);
    float wy = py - y0f, wx = px - x0f;

    const float* sp = in + (size_t)b * hi * wi;
    float r0 = sp[y0 * wi + x0] * (1.f - wx) + sp[y0 * wi + x1] * wx;
    float r1 = sp[y1 * wi + x0] * (1.f - wx) + sp[y1 * wi + x1] * wx;
    out[p] = r0 * (1.f - wy) + r1 * wy;
}

// ---------------------------------------------------------------------------
// softsplat scatter, BOTH directions in one launch. n = 2*BB*hw.
// zz layout [dir][b][hw]; acc per dir at accBase + dir*ACC_PER_DIR + accOff.
// ---------------------------------------------------------------------------
__global__ void splat_k(const float* __restrict__ fA, const float* __restrict__ fB,
                        const float* __restrict__ zz, const float* __restrict__ tvec,
                        float* __restrict__ accBase, size_t accOff,
                        int h, int w, int n)
{
    int p = blockIdx.x * 256 + threadIdx.x;
    if (p >= n) return;
    const int hw = h * w;
    const int bb = p / hw, pp = p % hw;
    const int dir = bb / BB, b = bb - dir * BB;
    const int y = pp / w, x = pp - y * w;

    const float* flow = dir ? fB : fA;
    float tt = tvec[b];
    if (dir) tt = 1.f - tt;
    float f0 = tt * flow[((size_t)b * 2 + 0) * hw + pp];
    float f1 = tt * flow[((size_t)b * 2 + 1) * hw + pp];
    float ez = expf(zz[(size_t)bb * hw + pp]);
    float v0 = -f0 * ez, v1 = -f1 * ez;

    float fx = (float)x + f0, fy = (float)y + f1;
    float x0f = floorf(fx), y0f = floorf(fy);
    int x0 = (int)x0f, y0 = (int)y0f;
    int x1 = x0 + 1, y1 = y0 + 1;
    float wx1 = fx - x0f, wy1 = fy - y0f;
    float wx0 = 1.f - wx1, wy0 = 1.f - wy1;

    float* a0 = accBase + (size_t)dir * ACC_PER_DIR + accOff + (size_t)b * 3 * hw;
    int cx[4] = {x0, x1, x0, x1};
    int cy[4] = {y0, y0, y1, y1};
    float cw[4] = {wx0 * wy0, wx1 * wy0, wx0 * wy1, wx1 * wy1};
#pragma unroll
    for (int k = 0; k < 4; k++) {
        if (cx[k] >= 0 && cx[k] < w && cy[k] >= 0 && cy[k] < h) {
            int q = cy[k] * w + cx[k];
            float wt = cw[k];
            atomicAdd(a0 + q, v0 * wt);
            atomicAdd(a0 + hw + q, v1 * wt);
            atomicAdd(a0 + 2 * hw + q, ez * wt);
        }
    }
}

// ---------------------------------------------------------------------------
// backwarp + inline flow normalization, BOTH directions (grid.z = dir).
// grid.y = channel chunk (8 each).
// ---------------------------------------------------------------------------
__global__ void backwarp_out_k(const float* __restrict__ srcA, const float* __restrict__ srcB,
                               int C, const float* __restrict__ accBase, size_t accOff,
                               float* __restrict__ out, int CT, int c0a, int c0b,
                               int h, int w, int n)
{
    int p = blockIdx.x * 256 + threadIdx.x;
    if (p >= n) return;
    const int dir = blockIdx.z;
    const int hw = h * w;
    const int b = p / hw, pp = p % hw;
    const int y = pp / w, x = pp - y * w;

    const float* src = dir ? srcB : srcA;
    const int c0 = dir ? c0b : c0a;
    const float* ab = accBase + (size_t)dir * ACC_PER_DIR + accOff + (size_t)b * 3 * hw;
    float d  = ab[2 * hw + pp] + EPS;
    float f0 = ab[pp] / d;
    float f1 = ab[hw + pp] / d;

    float px = fminf(fmaxf((float)x + f0, 0.f), (float)(w - 1));
    float py = fminf(fmaxf((float)y + f1, 0.f), (float)(h - 1));
    float x0f = floorf(px), y0f = floorf(py);
    int x0 = (int)x0f, y0 = (int)y0f;
    int x1 = min(x0 + 1, w - 1), y1 = min(y0 + 1, h - 1);
    float wx = px - x0f, wy = py - y0f;
    float w00 = (1.f - wx) * (1.f - wy), w10 = wx * (1.f - wy);
    float w01 = (1.f - wx) * wy,        w11 = wx * wy;

    int cbeg = blockIdx.y * 8;
    int cend = min(cbeg + 8, C);
#pragma unroll 4
    for (int c = cbeg; c < cend; c++) {
        const float* sp = src + ((size_t)b * C + c) * hw;
        float g = sp[y0 * w + x0] * w00 + sp[y0 * w + x1] * w10 +
                  sp[y1 * w + x0] * w01 + sp[y1 * w + x1] * w11;
        out[(((size_t)b * CT + c0 + c) * h + y) * w + x] = g;
    }
}

// ---------------------------------------------------------------------------
// Orchestration
// ---------------------------------------------------------------------------
static inline int cdiv(int a, int b) { return (a + b - 1) / b; }

static inline int conv_smem(int STRIDE, int PY, int CHUNK)
{
    int tsw = 16 * STRIDE + 2;
    int tsh = 8 * PY * STRIDE + 2;
    return 2 * CHUNK * (tsw * tsh + 288) * 4;
}

extern "C" void kernel_launch(void* const* d_in, const int* in_sizes, int n_in,
                              void* d_out, int out_size)
{
    const float* in0   = (const float*)d_in[0];
    const float* in1   = (const float*)d_in[1];
    const float* tvec  = (const float*)d_in[2];
    const float* f01[3] = {(const float*)d_in[3], (const float*)d_in[4], (const float*)d_in[5]};
    const float* f10[3] = {(const float*)d_in[6], (const float*)d_in[7], (const float*)d_in[8]};
    const float* W[6]  = {(const float*)d_in[9],  (const float*)d_in[11], (const float*)d_in[13],
                          (const float*)d_in[15], (const float*)d_in[17], (const float*)d_in[19]};
    const float* Bs[6] = {(const float*)d_in[10], (const float*)d_in[12], (const float*)d_in[14],
                          (const float*)d_in[16], (const float*)d_in[18], (const float*)d_in[20]};
    const float* prelu  = (const float*)d_in[21];
    const float* pscale = (const float*)d_in[22];
    float* out = (float*)d_out;

    float* S = nullptr;
    cudaGetSymbolAddress((void**)&S, g_scratch);

    const int sm1  = conv_smem(1, 4, 3);
    const int sm18 = conv_smem(1, 4, 8);
    const int sm28 = conv_smem(2, 2, 8);
    cudaFuncSetAttribute((const void*)conv3x3_k<3, 1, 4, 3>,  cudaFuncAttributeMaxDynamicSharedMemorySize, sm1);
    cudaFuncSetAttribute((const void*)conv3x3_k<32, 1, 4, 8>, cudaFuncAttributeMaxDynamicSharedMemorySize, sm18);
    cudaFuncSetAttribute((const void*)conv3x3_k<32, 2, 2, 8>, cudaFuncAttributeMaxDynamicSharedMemorySize, sm28);
    cudaFuncSetAttribute((const void*)conv3x3_k<64, 1, 4, 8>, cudaFuncAttributeMaxDynamicSharedMemorySize, sm18);
    cudaFuncSetAttribute((const void*)conv3x3_k<64, 2, 2, 8>, cudaFuncAttributeMaxDynamicSharedMemorySize, sm28);
    cudaFuncSetAttribute((const void*)conv3x3_k<96, 1, 4, 8>, cudaFuncAttributeMaxDynamicSharedMemorySize, sm18);

    cudaMemsetAsync(S + O_ACC, 0, sizeof(float) * ACC_TOTAL, 0);

    // ---- feature extraction (fp32, both images batched) ----
    conv3x3_k<3, 1, 4, 3><<<dim3(32, 16, 4), 256, sm1>>>(in0, in1, W[0], Bs[0], prelu, 0,
                                                          S + O_T1_0, S + O_T1_1, 512, 512, 32, 1);
    conv3x3_k<32, 1, 4, 8><<<dim3(32, 16, 4), 256, sm18>>>(S + O_T1_0, S + O_T1_1, W[1], Bs[1], prelu, 1,
                                                            S + O_F1_0, S + O_F1_1, 512, 512, 32, 1);
    conv3x3_k<32, 2, 2, 8><<<dim3(16, 16, 8), 256, sm28>>>(S + O_F1_0, S + O_F1_1, W[2], Bs[2], prelu, 2,
                                                            S + O_T2_0, S + O_T2_1, 512, 512, 64, 2);
    conv3x3_k<64, 1, 4, 8><<<dim3(16, 8, 8), 256, sm18>>>(S + O_T2_0, S + O_T2_1, W[3], Bs[3], prelu, 3,
                                                           S + O_F2_0, S + O_F2_1, 256, 256, 64, 2);
    conv3x3_k<64, 2, 2, 8><<<dim3(8, 8, 12), 256, sm28>>>(S + O_F2_0, S + O_F2_1, W[4], Bs[4], prelu, 4,
                                                           S + O_T3_0, S + O_T3_1, 256, 256, 96, 3);
    conv3x3_k<96, 1, 4, 8><<<dim3(8, 4, 12), 256, sm18>>>(S + O_T3_0, S + O_T3_1, W[5], Bs[5], prelu, 5,
                                                           S + O_F3_0, S + O_F3_1, 128, 128, 96, 3);

    float* L0 = out;                 // (B,70,512,512)
    float* L1 = out + 36700160ull;   // (B,128,256,256)
    float* L2 = out + 53477376ull;   // (B,192,128,128)

    const int hw0 = 512 * 512, hw1 = 256 * 256, hw2 = 128 * 128;

    // ---- z for both directions in one launch ----
    z_kernel<<<cdiv(2 * BB * hw0, 256), 256>>>(in0, in1, f01[0], f10[0], pscale,
                                               S + O_Z, 512, 512, 2 * BB * hw0);
    resize_k<<<cdiv(2 * BB * hw1, 256), 256>>>(S + O_Z, S + O_ZR1, 512, 512, 256, 256, 2 * BB * hw1);
    resize_k<<<cdiv(2 * BB * hw2, 256), 256>>>(S + O_Z, S + O_ZR2, 512, 512, 128, 128, 2 * BB * hw2);

    // ---- splats, both directions per launch ----
    splat_k<<<cdiv(2 * BB * hw0, 256), 256>>>(f01[0], f10[0], S + O_Z,  tvec, S + O_ACC, 0,       512, 512, 2 * BB * hw0);
    splat_k<<<cdiv(2 * BB * hw1, 256), 256>>>(f01[1], f10[1], S + O_ZR1, tvec, S + O_ACC, 1572864, 256, 256, 2 * BB * hw1);
    splat_k<<<cdiv(2 * BB * hw2, 256), 256>>>(f01[2], f10[2], S + O_ZR2, tvec, S + O_ACC, 1966080, 128, 128, 2 * BB * hw2);

    // ---- backwarps (normalization fused), both directions per launch ----
    backwarp_out_k<<<dim3(cdiv(BB * hw0, 256), 1, 2), 256>>>(in0, in1, 3,
        S + O_ACC, 0, L0, 70, 0, 35, 512, 512, BB * hw0);
    backwarp_out_k<<<dim3(cdiv(BB * hw0, 256), 4, 2), 256>>>(S + O_F1_0, S + O_F1_1, 32,
        S + O_ACC, 0, L0, 70, 3, 38, 512, 512, BB * hw0);
    backwarp_out_k<<<dim3(cdiv(BB * hw1, 256), 8, 2), 256>>>(S + O_F2_0, S + O_F2_1, 64,
        S + O_ACC, 1572864, L1, 128, 0, 64, 256, 256, BB * hw1);
    backwarp_out_k<<<dim3(cdiv(BB * hw2, 256), 12, 2), 256>>>(S + O_F3_0, S + O_F3_1, 96,
        S + O_ACC, 1966080, L2, 192, 0, 96, 128, 128, BB * hw2);
}